// round 7
// baseline (speedup 1.0000x reference)
#include <cuda_runtime.h>
#include <cstdint>

// ---------------------------------------------------------------------------
// GAT 4-layer network, N=50000 nodes, E=800000 edges (+ N self-loops).
// dims: 256 -> 32 -> 64 -> 128 -> 128 -> fc 40
// R7: proven 3-phase vectorized edge kernel (revert single-pass experiment);
//     fused-edot GEMM with per-shape __launch_bounds__ for occupancy/MLP.
// ---------------------------------------------------------------------------

#define NMAX 50000
#define EMAX 800000
#define CMAX 128
#define TOTE (EMAX + NMAX)

// -------------------- device scratch (allocation-free rule) ---------------
__device__ int      g_src[EMAX];
__device__ int      g_dst[EMAX];
__device__ int      g_cnt[NMAX];
__device__ int      g_rowptr[NMAX + 1];
__device__ int      g_cursor[NMAX];
__device__ int      g_csr_src[TOTE];
__device__ float    g_e[TOTE];
__device__ __align__(16) float g_h[(size_t)NMAX * CMAX];
__device__ __align__(16) float g_aggA[(size_t)NMAX * CMAX];
__device__ __align__(16) float g_aggB[(size_t)NMAX * CMAX];
__device__ float    g_es[NMAX];
__device__ float    g_ed[NMAX];
__device__ int      g_is64;

// -------------------- detect edge dtype + init counts ---------------------
__global__ void detect_init_kernel(const void* eptr, int n) {
    int i = blockIdx.x * blockDim.x + threadIdx.x;
    if (i < n) g_cnt[i] = 1;              // self-loop pre-counted
    if (i == 0) {
        const int* p = (const int*)eptr;
        int all0 = 1;
        for (int k = 1; k < 128; k += 2)
            if (p[k] != 0) all0 = 0;
        g_is64 = all0;   // int64 little-endian, values < 2^31 -> odd words 0
    }
}

// -------------------- convert + count (fused) ------------------------------
__global__ void convert_count_kernel(const void* eptr, int E) {
    int i = blockIdx.x * blockDim.x + threadIdx.x;
    if (i >= E) return;
    int s, d;
    if (g_is64) {
        const long long* p = (const long long*)eptr;
        s = (int)p[i];
        d = (int)p[E + i];
    } else {
        const int* p = (const int*)eptr;
        s = p[i];
        d = p[E + i];
    }
    g_src[i] = s;
    g_dst[i] = d;
    atomicAdd(&g_cnt[d], 1);
}

// -------------------- single-block exclusive scan over g_cnt --------------
__global__ void scan_kernel(int n) {
    const int T = 1024;
    int tid = threadIdx.x;
    int C = (n + T - 1) / T;
    int base = tid * C;
    int end = min(base + C, n);

    int s = 0;
    for (int k = base; k < end; k++) s += g_cnt[k];

    int lane = tid & 31, w = tid >> 5;
    unsigned full = 0xffffffffu;
    int x = s;
#pragma unroll
    for (int o = 1; o < 32; o <<= 1) {
        int y = __shfl_up_sync(full, x, o);
        if (lane >= o) x += y;
    }
    __shared__ int wsum[32];
    __shared__ int woff[32];
    if (lane == 31) wsum[w] = x;
    __syncthreads();
    if (tid < 32) {
        int v = wsum[tid];
        int xx = v;
#pragma unroll
        for (int o = 1; o < 32; o <<= 1) {
            int y = __shfl_up_sync(full, xx, o);
            if (tid >= o) xx += y;
        }
        woff[tid] = xx - v;
    }
    __syncthreads();
    int running = x - s + woff[w];

    for (int k = base; k < end; k++) {
        g_rowptr[k] = running;
        g_cursor[k] = running;
        running += g_cnt[k];
    }
    if (end == n && base < n) g_rowptr[n] = running;
}

__global__ void scatter_kernel(int E, int n) {
    int idx = blockIdx.x * blockDim.x + threadIdx.x;
    if (idx >= E + n) return;
    int s, d;
    if (idx < E) { s = g_src[idx]; d = g_dst[idx]; }
    else         { s = d = idx - E; }
    int pos = atomicAdd(&g_cursor[d], 1);
    g_csr_src[pos] = s;
}

// -------------------- GEMM + fused edot: h = act(in)@W; es,ed dots --------
template <int CIN, int COUT, bool RELU, int MINB>
__global__ void __launch_bounds__(256, MINB)
gemm_kernel(const float* __restrict__ in,
            const float* __restrict__ W,
            const float* __restrict__ as_,
            const float* __restrict__ ad_, int n) {
    constexpr int TX = COUT / 4;       // threads along column dim (float4 each)
    constexpr int TY = 256 / TX;       // thread-rows per block
    constexpr int R  = 4;              // rows per thread
    extern __shared__ float4 Ws[];     // CIN * TX float4

    int tid = threadIdx.x;
    const float4* W4 = reinterpret_cast<const float4*>(W);
    for (int i = tid; i < CIN * TX; i += 256) Ws[i] = W4[i];
    __syncthreads();

    int tx = tid % TX;
    int ty = tid / TX;
    int row0 = (blockIdx.x * TY + ty) * R;

    const float4* inp[R];
#pragma unroll
    for (int r = 0; r < R; r++) {
        int rc = min(row0 + r, n - 1);
        inp[r] = reinterpret_cast<const float4*>(in + (size_t)rc * CIN);
    }

    float4 acc[R];
#pragma unroll
    for (int r = 0; r < R; r++) acc[r] = make_float4(0.f, 0.f, 0.f, 0.f);

#pragma unroll 2
    for (int k4 = 0; k4 < CIN / 4; k4++) {
        float4 xv[R];
#pragma unroll
        for (int r = 0; r < R; r++) {
            xv[r] = __ldg(&inp[r][k4]);
            if (RELU) {
                xv[r].x = fmaxf(xv[r].x, 0.f); xv[r].y = fmaxf(xv[r].y, 0.f);
                xv[r].z = fmaxf(xv[r].z, 0.f); xv[r].w = fmaxf(xv[r].w, 0.f);
            }
        }
#pragma unroll
        for (int j = 0; j < 4; j++) {
            float4 w = Ws[(k4 * 4 + j) * TX + tx];
#pragma unroll
            for (int r = 0; r < R; r++) {
                float xs = (j == 0) ? xv[r].x : (j == 1) ? xv[r].y
                         : (j == 2) ? xv[r].z : xv[r].w;
                acc[r].x = fmaf(xs, w.x, acc[r].x);
                acc[r].y = fmaf(xs, w.y, acc[r].y);
                acc[r].z = fmaf(xs, w.z, acc[r].z);
                acc[r].w = fmaf(xs, w.w, acc[r].w);
            }
        }
    }

    // store h
    float4* out4 = reinterpret_cast<float4*>(g_h);
#pragma unroll
    for (int r = 0; r < R; r++) {
        int row = row0 + r;
        if (row < n) out4[(size_t)row * TX + tx] = acc[r];
    }

    // fused edot: es[row] = h[row].a_src, ed[row] = h[row].a_dst
    const float4* as4 = reinterpret_cast<const float4*>(as_);
    const float4* ad4 = reinterpret_cast<const float4*>(ad_);
    float4 av = __ldg(&as4[tx]);
    float4 dv = __ldg(&ad4[tx]);
#pragma unroll
    for (int r = 0; r < R; r++) {
        float ps = acc[r].x * av.x + acc[r].y * av.y
                 + acc[r].z * av.z + acc[r].w * av.w;
        float pd = acc[r].x * dv.x + acc[r].y * dv.y
                 + acc[r].z * dv.z + acc[r].w * dv.w;
#pragma unroll
        for (int off = TX / 2; off > 0; off >>= 1) {
            ps += __shfl_down_sync(0xffffffffu, ps, off, TX);
            pd += __shfl_down_sync(0xffffffffu, pd, off, TX);
        }
        int row = row0 + r;
        if (tx == 0 && row < n) { g_es[row] = ps; g_ed[row] = pd; }
    }
}

// -------------------- vector helpers --------------------------------------
template <int V> struct VecT;
template <> struct VecT<1> { using T = float; };
template <> struct VecT<2> { using T = float2; };
template <> struct VecT<4> { using T = float4; };

__device__ __forceinline__ void vfma(float& a, float al, float v) {
    a = fmaf(al, v, a);
}
__device__ __forceinline__ void vfma(float2& a, float al, float2 v) {
    a.x = fmaf(al, v.x, a.x); a.y = fmaf(al, v.y, a.y);
}
__device__ __forceinline__ void vfma(float4& a, float al, float4 v) {
    a.x = fmaf(al, v.x, a.x); a.y = fmaf(al, v.y, a.y);
    a.z = fmaf(al, v.z, a.z); a.w = fmaf(al, v.w, a.w);
}

// -------------------- fused edge phase: 3-phase softmax + aggregate -------
// (proven R2/R4 structure: warp per dst, vectorized gathers, one exp/edge)
template <int COUT>
__global__ void gat_edge_kernel(const float* __restrict__ b,
                                float* __restrict__ agg, int n) {
    constexpr int V = COUT / 32;
    using VT = typename VecT<V>::T;
    const unsigned full = 0xffffffffu;
    int lane = threadIdx.x & 31;
    int d = blockIdx.x * 8 + (threadIdx.x >> 5);
    if (d >= n) return;

    int r0 = g_rowptr[d];
    int r1 = g_rowptr[d + 1];
    float edd = g_ed[d];

    // phase 1: e = leaky_relu(es[src]+ed[dst]); warp max
    float mx = -3.4e38f;
    for (int i = r0 + lane; i < r1; i += 32) {
        float e = __ldg(&g_es[__ldg(&g_csr_src[i])]) + edd;
        e = (e > 0.f) ? e : 0.2f * e;
        g_e[i] = e;
        mx = fmaxf(mx, e);
    }
#pragma unroll
    for (int o = 16; o; o >>= 1)
        mx = fmaxf(mx, __shfl_xor_sync(full, mx, o));

    // phase 2: exp once per edge, store; warp sum
    float sum = 0.f;
    for (int i = r0 + lane; i < r1; i += 32) {
        float ex = __expf(g_e[i] - mx);
        g_e[i] = ex;
        sum += ex;
    }
#pragma unroll
    for (int o = 16; o; o >>= 1)
        sum += __shfl_xor_sync(full, sum, o);
    float invS = 1.0f / sum;
    __syncwarp();

    // phase 3: agg[d] = bias + sum alpha * h[src]   (lane owns V columns)
    const VT* bv = reinterpret_cast<const VT*>(b);
    VT acc = __ldg(&bv[lane]);
    const VT* hv = reinterpret_cast<const VT*>(g_h);

#pragma unroll 4
    for (int i = r0; i < r1; i++) {
        int s = __ldg(&g_csr_src[i]);
        float a = __ldg(&g_e[i]) * invS;
        VT v = __ldg(&hv[(size_t)s * 32 + lane]);
        vfma(acc, a, v);
    }

    reinterpret_cast<VT*>(agg)[(size_t)d * 32 + lane] = acc;
}

// -------------------- final FC: out = relu(agg4) @ fcW + fcb --------------
__global__ void fc_kernel(const float* __restrict__ in,
                          const float* __restrict__ fcW,
                          const float* __restrict__ fcb,
                          float* __restrict__ out, int n) {
    __shared__ float Ws[128 * 40];
    int tid = threadIdx.x;                 // blockDim = 320
    for (int i = tid; i < 128 * 40; i += 320) Ws[i] = fcW[i];
    __syncthreads();
    int tx = tid % 40;
    int ty = tid / 40;                     // 8 rows/block
    int row = blockIdx.x * 8 + ty;
    if (row >= n) return;
    const float* irow = in + (size_t)row * 128;
    float acc = 0.f;
#pragma unroll 8
    for (int k = 0; k < 128; k++) {
        float v = fmaxf(irow[k], 0.f);
        acc = fmaf(v, Ws[k * 40 + tx], acc);
    }
    out[(size_t)row * 40 + tx] = acc + fcb[tx];
}

// ---------------------------------------------------------------------------
// host driver
// ---------------------------------------------------------------------------
static inline int ceil_div(int a, int b) { return (a + b - 1) / b; }

template <int CIN, int COUT, bool RELU, int MINB>
static void launch_gemm(const float* in, const float* W,
                        const float* as_, const float* ad_, int n) {
    constexpr int TX = COUT / 4;
    constexpr int TY = 256 / TX;
    constexpr int R  = 4;
    size_t smem = (size_t)CIN * TX * sizeof(float4);
    if (smem > 48 * 1024) {
        cudaFuncSetAttribute(
            (const void*)gemm_kernel<CIN, COUT, RELU, MINB>,
            cudaFuncAttributeMaxDynamicSharedMemorySize, (int)smem);
    }
    gemm_kernel<CIN, COUT, RELU, MINB><<<ceil_div(n, TY * R), 256, smem>>>(
        in, W, as_, ad_, n);
}

extern "C" void kernel_launch(void* const* d_in, const int* in_sizes, int n_in,
                              void* d_out, int out_size) {
    const float* x   = (const float*)d_in[0];
    const void*  ei  = d_in[1];
    const float* W1  = (const float*)d_in[2];
    const float* a1s = (const float*)d_in[3];
    const float* a1d = (const float*)d_in[4];
    const float* b1  = (const float*)d_in[5];
    const float* W2  = (const float*)d_in[6];
    const float* a2s = (const float*)d_in[7];
    const float* a2d = (const float*)d_in[8];
    const float* b2  = (const float*)d_in[9];
    const float* W3  = (const float*)d_in[10];
    const float* a3s = (const float*)d_in[11];
    const float* a3d = (const float*)d_in[12];
    const float* b3  = (const float*)d_in[13];
    const float* W4  = (const float*)d_in[14];
    const float* a4s = (const float*)d_in[15];
    const float* a4d = (const float*)d_in[16];
    const float* b4  = (const float*)d_in[17];
    const float* fcW = (const float*)d_in[18];
    const float* fcb = (const float*)d_in[19];

    const int n = in_sizes[0] / 256;
    const int E = in_sizes[1] / 2;
    const int tot = E + n;

    float* aggA; cudaGetSymbolAddress((void**)&aggA, g_aggA);
    float* aggB; cudaGetSymbolAddress((void**)&aggB, g_aggB);

    // ---- preprocessing; gemm1 placed 4th in stream order for profiling ----
    detect_init_kernel<<<ceil_div(n, 256), 256>>>(ei, n);        // 1
    convert_count_kernel<<<ceil_div(E, 256), 256>>>(ei, E);      // 2
    scan_kernel<<<1, 1024>>>(n);                                 // 3
    launch_gemm<256, 32, false, 5>(x, W1, a1s, a1d, n);          // 4 (profiled)
    scatter_kernel<<<ceil_div(tot, 256), 256>>>(E, n);           // 5

    // ---- layer 1: 256 -> 32 ----
    gat_edge_kernel<32><<<ceil_div(n, 8), 256>>>(b1, aggA, n);

    // ---- layer 2: 32 -> 64 ----
    launch_gemm<32, 64, true, 6>(aggA, W2, a2s, a2d, n);
    gat_edge_kernel<64><<<ceil_div(n, 8), 256>>>(b2, aggB, n);

    // ---- layer 3: 64 -> 128 ----
    launch_gemm<64, 128, true, 5>(aggB, W3, a3s, a3d, n);
    gat_edge_kernel<128><<<ceil_div(n, 8), 256>>>(b3, aggA, n);

    // ---- layer 4: 128 -> 128 ----
    launch_gemm<128, 128, true, 3>(aggA, W4, a4s, a4d, n);
    gat_edge_kernel<128><<<ceil_div(n, 8), 256>>>(b4, aggB, n);

    // ---- final fc: relu(agg4) @ fcW + fcb ----
    fc_kernel<<<ceil_div(n, 8), 320>>>(aggB, fcW, fcb, (float*)d_out, n);
}

// round 8
// speedup vs baseline: 1.0501x; 1.0501x over previous
#include <cuda_runtime.h>
#include <cstdint>

// ---------------------------------------------------------------------------
// GAT 4-layer network, N=50000 nodes, E=800000 edges (+ N self-loops).
// dims: 256 -> 32 -> 64 -> 128 -> 128 -> fc 40
// R8: exact R2 edge kernel (424us champion) + measured-good fused-edot GEMM
//     (no launch_bounds) + slim preprocess. No other changes.
// ---------------------------------------------------------------------------

#define NMAX 50000
#define EMAX 800000
#define CMAX 128
#define TOTE (EMAX + NMAX)

// -------------------- device scratch (allocation-free rule) ---------------
__device__ int      g_src[EMAX];
__device__ int      g_dst[EMAX];
__device__ int      g_cnt[NMAX];
__device__ int      g_rowptr[NMAX + 1];
__device__ int      g_cursor[NMAX];
__device__ int      g_csr_src[TOTE];
__device__ float    g_e[TOTE];
__device__ __align__(16) float g_h[(size_t)NMAX * CMAX];
__device__ __align__(16) float g_aggA[(size_t)NMAX * CMAX];
__device__ __align__(16) float g_aggB[(size_t)NMAX * CMAX];
__device__ float    g_es[NMAX];
__device__ float    g_ed[NMAX];
__device__ int      g_is64;

// -------------------- detect edge dtype + init counts ---------------------
__global__ void detect_init_kernel(const void* eptr, int n) {
    int i = blockIdx.x * blockDim.x + threadIdx.x;
    if (i < n) g_cnt[i] = 1;              // self-loop pre-counted
    if (i == 0) {
        const int* p = (const int*)eptr;
        int all0 = 1;
        for (int k = 1; k < 128; k += 2)
            if (p[k] != 0) all0 = 0;
        g_is64 = all0;   // int64 little-endian, values < 2^31 -> odd words 0
    }
}

// -------------------- convert + count (fused) ------------------------------
__global__ void convert_count_kernel(const void* eptr, int E) {
    int i = blockIdx.x * blockDim.x + threadIdx.x;
    if (i >= E) return;
    int s, d;
    if (g_is64) {
        const long long* p = (const long long*)eptr;
        s = (int)p[i];
        d = (int)p[E + i];
    } else {
        const int* p = (const int*)eptr;
        s = p[i];
        d = p[E + i];
    }
    g_src[i] = s;
    g_dst[i] = d;
    atomicAdd(&g_cnt[d], 1);
}

// -------------------- single-block exclusive scan over g_cnt --------------
__global__ void scan_kernel(int n) {
    const int T = 1024;
    int tid = threadIdx.x;
    int C = (n + T - 1) / T;
    int base = tid * C;
    int end = min(base + C, n);

    int s = 0;
    for (int k = base; k < end; k++) s += g_cnt[k];

    int lane = tid & 31, w = tid >> 5;
    unsigned full = 0xffffffffu;
    int x = s;
#pragma unroll
    for (int o = 1; o < 32; o <<= 1) {
        int y = __shfl_up_sync(full, x, o);
        if (lane >= o) x += y;
    }
    __shared__ int wsum[32];
    __shared__ int woff[32];
    if (lane == 31) wsum[w] = x;
    __syncthreads();
    if (tid < 32) {
        int v = wsum[tid];
        int xx = v;
#pragma unroll
        for (int o = 1; o < 32; o <<= 1) {
            int y = __shfl_up_sync(full, xx, o);
            if (tid >= o) xx += y;
        }
        woff[tid] = xx - v;
    }
    __syncthreads();
    int running = x - s + woff[w];

    for (int k = base; k < end; k++) {
        g_rowptr[k] = running;
        g_cursor[k] = running;
        running += g_cnt[k];
    }
    if (end == n && base < n) g_rowptr[n] = running;
}

__global__ void scatter_kernel(int E, int n) {
    int idx = blockIdx.x * blockDim.x + threadIdx.x;
    if (idx >= E + n) return;
    int s, d;
    if (idx < E) { s = g_src[idx]; d = g_dst[idx]; }
    else         { s = d = idx - E; }
    int pos = atomicAdd(&g_cursor[d], 1);
    g_csr_src[pos] = s;
}

// -------------------- GEMM + fused edot: h = act(in)@W; es,ed dots --------
// (verbatim R5/R6 version — measured 35.0us on gemm1, no launch bounds)
template <int CIN, int COUT, bool RELU>
__global__ void gemm_kernel(const float* __restrict__ in,
                            const float* __restrict__ W,
                            const float* __restrict__ as_,
                            const float* __restrict__ ad_, int n) {
    constexpr int TX = COUT / 4;       // threads along column dim (float4 each)
    constexpr int TY = 256 / TX;       // thread-rows per block
    constexpr int R  = 4;              // rows per thread
    extern __shared__ float4 Ws[];     // CIN * TX float4

    int tid = threadIdx.x;
    const float4* W4 = reinterpret_cast<const float4*>(W);
    for (int i = tid; i < CIN * TX; i += 256) Ws[i] = W4[i];
    __syncthreads();

    int tx = tid % TX;
    int ty = tid / TX;
    int row0 = (blockIdx.x * TY + ty) * R;

    const float4* inp[R];
#pragma unroll
    for (int r = 0; r < R; r++) {
        int rc = min(row0 + r, n - 1);
        inp[r] = reinterpret_cast<const float4*>(in + (size_t)rc * CIN);
    }

    float4 acc[R];
#pragma unroll
    for (int r = 0; r < R; r++) acc[r] = make_float4(0.f, 0.f, 0.f, 0.f);

#pragma unroll 2
    for (int k4 = 0; k4 < CIN / 4; k4++) {
        float4 xv[R];
#pragma unroll
        for (int r = 0; r < R; r++) {
            xv[r] = __ldg(&inp[r][k4]);
            if (RELU) {
                xv[r].x = fmaxf(xv[r].x, 0.f); xv[r].y = fmaxf(xv[r].y, 0.f);
                xv[r].z = fmaxf(xv[r].z, 0.f); xv[r].w = fmaxf(xv[r].w, 0.f);
            }
        }
#pragma unroll
        for (int j = 0; j < 4; j++) {
            float4 w = Ws[(k4 * 4 + j) * TX + tx];
#pragma unroll
            for (int r = 0; r < R; r++) {
                float xs = (j == 0) ? xv[r].x : (j == 1) ? xv[r].y
                         : (j == 2) ? xv[r].z : xv[r].w;
                acc[r].x = fmaf(xs, w.x, acc[r].x);
                acc[r].y = fmaf(xs, w.y, acc[r].y);
                acc[r].z = fmaf(xs, w.z, acc[r].z);
                acc[r].w = fmaf(xs, w.w, acc[r].w);
            }
        }
    }

    // store h
    float4* out4 = reinterpret_cast<float4*>(g_h);
#pragma unroll
    for (int r = 0; r < R; r++) {
        int row = row0 + r;
        if (row < n) out4[(size_t)row * TX + tx] = acc[r];
    }

    // fused edot: es[row] = h[row].a_src, ed[row] = h[row].a_dst
    const float4* as4 = reinterpret_cast<const float4*>(as_);
    const float4* ad4 = reinterpret_cast<const float4*>(ad_);
    float4 av = __ldg(&as4[tx]);
    float4 dv = __ldg(&ad4[tx]);
#pragma unroll
    for (int r = 0; r < R; r++) {
        float ps = acc[r].x * av.x + acc[r].y * av.y
                 + acc[r].z * av.z + acc[r].w * av.w;
        float pd = acc[r].x * dv.x + acc[r].y * dv.y
                 + acc[r].z * dv.z + acc[r].w * dv.w;
#pragma unroll
        for (int off = TX / 2; off > 0; off >>= 1) {
            ps += __shfl_down_sync(0xffffffffu, ps, off, TX);
            pd += __shfl_down_sync(0xffffffffu, pd, off, TX);
        }
        int row = row0 + r;
        if (tx == 0 && row < n) { g_es[row] = ps; g_ed[row] = pd; }
    }
}

// -------------------- fused edge phase: softmax + aggregate (warp/dst) ----
// VERBATIM from R2 (the 424us champion).
template <int COUT>
__global__ void gat_edge_kernel(const float* __restrict__ b,
                                float* __restrict__ agg, int n) {
    constexpr int RC = COUT / 32;
    int lane = threadIdx.x & 31;
    int d = blockIdx.x * 8 + (threadIdx.x >> 5);
    if (d >= n) return;

    int r0 = g_rowptr[d];
    int r1 = g_rowptr[d + 1];
    float edd = g_ed[d];

    // phase 1: e = leaky_relu(es[src] + ed[dst]); warp max
    float mx = -3.4e38f;
    for (int i = r0 + lane; i < r1; i += 32) {
        float e = g_es[g_csr_src[i]] + edd;
        e = (e > 0.f) ? e : 0.2f * e;
        g_e[i] = e;
        mx = fmaxf(mx, e);
    }
#pragma unroll
    for (int o = 16; o; o >>= 1) mx = fmaxf(mx, __shfl_xor_sync(0xffffffffu, mx, o));

    // phase 2: exp + warp sum
    float sum = 0.f;
    for (int i = r0 + lane; i < r1; i += 32) {
        float ex = __expf(g_e[i] - mx);
        g_e[i] = ex;
        sum += ex;
    }
#pragma unroll
    for (int o = 16; o; o >>= 1) sum += __shfl_xor_sync(0xffffffffu, sum, o);
    float inv = 1.0f / sum;
    __syncwarp();

    // phase 3: agg[d] = bias + sum alpha * h[src]   (lane owns columns)
    float acc[RC];
#pragma unroll
    for (int r = 0; r < RC; r++) acc[r] = __ldg(&b[lane + 32 * r]);

    for (int i = r0; i < r1; i++) {
        int s = g_csr_src[i];
        float alpha = g_e[i] * inv;
        const float* hp = g_h + (size_t)s * COUT + lane;
#pragma unroll
        for (int r = 0; r < RC; r++)
            acc[r] = fmaf(alpha, hp[32 * r], acc[r]);
    }

    float* op = agg + (size_t)d * COUT + lane;
#pragma unroll
    for (int r = 0; r < RC; r++) op[32 * r] = acc[r];
}

// -------------------- final FC: out = relu(agg4) @ fcW + fcb --------------
__global__ void fc_kernel(const float* __restrict__ in,
                          const float* __restrict__ fcW,
                          const float* __restrict__ fcb,
                          float* __restrict__ out, int n) {
    __shared__ float Ws[128 * 40];
    int tid = threadIdx.x;                 // blockDim = 320
    for (int i = tid; i < 128 * 40; i += 320) Ws[i] = fcW[i];
    __syncthreads();
    int tx = tid % 40;
    int ty = tid / 40;                     // 8 rows/block
    int row = blockIdx.x * 8 + ty;
    if (row >= n) return;
    const float* irow = in + (size_t)row * 128;
    float acc = 0.f;
#pragma unroll 8
    for (int k = 0; k < 128; k++) {
        float v = fmaxf(irow[k], 0.f);
        acc = fmaf(v, Ws[k * 40 + tx], acc);
    }
    out[(size_t)row * 40 + tx] = acc + fcb[tx];
}

// ---------------------------------------------------------------------------
// host driver
// ---------------------------------------------------------------------------
static inline int ceil_div(int a, int b) { return (a + b - 1) / b; }

template <int CIN, int COUT, bool RELU>
static void launch_gemm(const float* in, const float* W,
                        const float* as_, const float* ad_, int n) {
    constexpr int TX = COUT / 4;
    constexpr int TY = 256 / TX;
    constexpr int R  = 4;
    size_t smem = (size_t)CIN * TX * sizeof(float4);
    if (smem > 48 * 1024) {
        cudaFuncSetAttribute(
            (const void*)gemm_kernel<CIN, COUT, RELU>,
            cudaFuncAttributeMaxDynamicSharedMemorySize, (int)smem);
    }
    gemm_kernel<CIN, COUT, RELU><<<ceil_div(n, TY * R), 256, smem>>>(
        in, W, as_, ad_, n);
}

extern "C" void kernel_launch(void* const* d_in, const int* in_sizes, int n_in,
                              void* d_out, int out_size) {
    const float* x   = (const float*)d_in[0];
    const void*  ei  = d_in[1];
    const float* W1  = (const float*)d_in[2];
    const float* a1s = (const float*)d_in[3];
    const float* a1d = (const float*)d_in[4];
    const float* b1  = (const float*)d_in[5];
    const float* W2  = (const float*)d_in[6];
    const float* a2s = (const float*)d_in[7];
    const float* a2d = (const float*)d_in[8];
    const float* b2  = (const float*)d_in[9];
    const float* W3  = (const float*)d_in[10];
    const float* a3s = (const float*)d_in[11];
    const float* a3d = (const float*)d_in[12];
    const float* b3  = (const float*)d_in[13];
    const float* W4  = (const float*)d_in[14];
    const float* a4s = (const float*)d_in[15];
    const float* a4d = (const float*)d_in[16];
    const float* b4  = (const float*)d_in[17];
    const float* fcW = (const float*)d_in[18];
    const float* fcb = (const float*)d_in[19];

    const int n = in_sizes[0] / 256;
    const int E = in_sizes[1] / 2;
    const int tot = E + n;

    float* aggA; cudaGetSymbolAddress((void**)&aggA, g_aggA);
    float* aggB; cudaGetSymbolAddress((void**)&aggB, g_aggB);

    // ---- preprocessing; gemm1 placed 4th in stream order for profiling ----
    detect_init_kernel<<<ceil_div(n, 256), 256>>>(ei, n);        // 1
    convert_count_kernel<<<ceil_div(E, 256), 256>>>(ei, E);      // 2
    scan_kernel<<<1, 1024>>>(n);                                 // 3
    launch_gemm<256, 32, false>(x, W1, a1s, a1d, n);             // 4 (profiled)
    scatter_kernel<<<ceil_div(tot, 256), 256>>>(E, n);           // 5

    // ---- layer 1: 256 -> 32 ----
    gat_edge_kernel<32><<<ceil_div(n, 8), 256>>>(b1, aggA, n);

    // ---- layer 2: 32 -> 64 ----
    launch_gemm<32, 64, true>(aggA, W2, a2s, a2d, n);
    gat_edge_kernel<64><<<ceil_div(n, 8), 256>>>(b2, aggB, n);

    // ---- layer 3: 64 -> 128 ----
    launch_gemm<64, 128, true>(aggB, W3, a3s, a3d, n);
    gat_edge_kernel<128><<<ceil_div(n, 8), 256>>>(b3, aggA, n);

    // ---- layer 4: 128 -> 128 ----
    launch_gemm<128, 128, true>(aggA, W4, a4s, a4d, n);
    gat_edge_kernel<128><<<ceil_div(n, 8), 256>>>(b4, aggB, n);

    // ---- final fc: relu(agg4) @ fcW + fcb ----
    fc_kernel<<<ceil_div(n, 8), 320>>>(aggB, fcW, fcb, (float*)d_out, n);
}